// round 2
// baseline (speedup 1.0000x reference)
#include <cuda_runtime.h>
#include <cuda_bf16.h>

// Problem constants
#define BB 4
#define LL 2048
#define DD 8192
#define KK 4
#define TS 32           // timesteps per thread (sliding window)
#define THREADS 256     // threads per block; each owns 4 channels (float4)

// Output layout assumed: [q (B,L,2048) | k (B,L,2048) | v (B,L,4096) | new_cache (B,D,4)]
#define QK_W 2048
#define V_W  4096
#define Q_SIZE   ((size_t)BB * LL * QK_W)          // 16,777,216
#define V_SIZE   ((size_t)BB * LL * V_W)           // 33,554,432
#define CACHE_OFF (2 * Q_SIZE + V_SIZE)            // 67,108,864

__device__ __forceinline__ float silu_f(float v) {
    return v / (1.0f + __expf(-v));
}

__global__ void __launch_bounds__(THREADS)
conv_silu_kernel(const float* __restrict__ x,
                 const float* __restrict__ cache,
                 const float* __restrict__ w,
                 float* __restrict__ out)
{
    const int b  = blockIdx.z;
    const int t0 = blockIdx.y * TS;
    const int d  = (blockIdx.x * THREADS + threadIdx.x) * 4;   // channel group start

    // Per-channel taps: weight is (D, K) row-major, so w + (d+j)*4 is a float4 of taps.
    const float4 wr0 = *reinterpret_cast<const float4*>(w + (size_t)(d + 0) * KK);
    const float4 wr1 = *reinterpret_cast<const float4*>(w + (size_t)(d + 1) * KK);
    const float4 wr2 = *reinterpret_cast<const float4*>(w + (size_t)(d + 2) * KK);
    const float4 wr3 = *reinterpret_cast<const float4*>(w + (size_t)(d + 3) * KK);

    // Sliding window: m3 = X[t-3], m2 = X[t-2], m1 = X[t-1] (per-channel float4)
    float4 m3, m2, m1;
    const float* xb = x + (size_t)b * LL * DD + d;   // x[b, 0, d]

    if (t0 == 0) {
        // Seed from cache[b, d+j, kk], kk = 1,2,3  (cache layout (B,D,K))
        const float* cb = cache + ((size_t)b * DD + d) * KK;
        m3 = make_float4(cb[0*KK + 1], cb[1*KK + 1], cb[2*KK + 1], cb[3*KK + 1]);
        m2 = make_float4(cb[0*KK + 2], cb[1*KK + 2], cb[2*KK + 2], cb[3*KK + 2]);
        m1 = make_float4(cb[0*KK + 3], cb[1*KK + 3], cb[2*KK + 3], cb[3*KK + 3]);
    } else {
        m3 = *reinterpret_cast<const float4*>(xb + (size_t)(t0 - 3) * DD);
        m2 = *reinterpret_cast<const float4*>(xb + (size_t)(t0 - 2) * DD);
        m1 = *reinterpret_cast<const float4*>(xb + (size_t)(t0 - 1) * DD);
    }

    // Route channel group to q / k / v segment
    float* obase;
    int seg_d, seg_w;
    size_t boff;
    if (d < QK_W) {
        obase = out;                 seg_d = d;          seg_w = QK_W;
        boff  = (size_t)b * LL * QK_W;
    } else if (d < 2 * QK_W) {
        obase = out + Q_SIZE;        seg_d = d - QK_W;   seg_w = QK_W;
        boff  = (size_t)b * LL * QK_W;
    } else {
        obase = out + 2 * Q_SIZE;    seg_d = d - 2*QK_W; seg_w = V_W;
        boff  = (size_t)b * LL * V_W;
    }
    float* op = obase + boff + (size_t)t0 * seg_w + seg_d;

    const float* xp = xb + (size_t)t0 * DD;

    #pragma unroll
    for (int i = 0; i < TS; i++) {
        const float4 cur = *reinterpret_cast<const float4*>(xp + (size_t)i * DD);

        float4 y;
        y.x = wr0.x * m3.x + wr0.y * m2.x + wr0.z * m1.x + wr0.w * cur.x;
        y.y = wr1.x * m3.y + wr1.y * m2.y + wr1.z * m1.y + wr1.w * cur.y;
        y.z = wr2.x * m3.z + wr2.y * m2.z + wr2.z * m1.z + wr2.w * cur.z;
        y.w = wr3.x * m3.w + wr3.y * m2.w + wr3.z * m1.w + wr3.w * cur.w;

        y.x = silu_f(y.x);
        y.y = silu_f(y.y);
        y.z = silu_f(y.z);
        y.w = silu_f(y.w);

        *reinterpret_cast<float4*>(op + (size_t)i * seg_w) = y;

        m3 = m2; m2 = m1; m1 = cur;
    }
}

// new_cache[b, d, kk] = x[b, L-4+kk, d]  → one float4 store per (b,d)
__global__ void __launch_bounds__(256)
cache_kernel(const float* __restrict__ x, float* __restrict__ out_cache)
{
    const int idx = blockIdx.x * blockDim.x + threadIdx.x;   // b*D + d
    if (idx >= BB * DD) return;
    const int b = idx / DD;
    const int dch = idx % DD;
    const float* xp = x + ((size_t)b * LL + (LL - KK)) * DD + dch;
    float4 v;
    v.x = xp[0 * (size_t)DD];
    v.y = xp[1 * (size_t)DD];
    v.z = xp[2 * (size_t)DD];
    v.w = xp[3 * (size_t)DD];
    reinterpret_cast<float4*>(out_cache)[idx] = v;
}

extern "C" void kernel_launch(void* const* d_in, const int* in_sizes, int n_in,
                              void* d_out, int out_size)
{
    const float* x     = (const float*)d_in[0];
    const float* cache = (const float*)d_in[1];
    const float* w     = (const float*)d_in[2];
    float* out = (float*)d_out;

    dim3 grid(DD / (4 * THREADS), LL / TS, BB);   // (8, 64, 4)
    conv_silu_kernel<<<grid, THREADS>>>(x, cache, w, out);

    cache_kernel<<<(BB * DD + 255) / 256, 256>>>(x, out + CACHE_OFF);
}

// round 5
// speedup vs baseline: 1.0163x; 1.0163x over previous
#include <cuda_runtime.h>
#include <cuda_bf16.h>

// Problem constants
#define BB 4
#define LL 2048
#define DD 8192
#define KK 4
#define TS 64           // timesteps per thread (sliding window)
#define UNR 8           // inner unroll (caps in-flight loads / register pressure)
#define THREADS 256     // threads per block; each owns 4 channels (float4)

// Output layout: [q (B,L,2048) | k (B,L,2048) | v (B,L,4096) | new_cache (B,D,4)]
#define QK_W 2048
#define V_W  4096
#define Q_SIZE   ((size_t)BB * LL * QK_W)          // 16,777,216
#define V_SIZE   ((size_t)BB * LL * V_W)           // 33,554,432
#define CACHE_OFF (2 * Q_SIZE + V_SIZE)            // 67,108,864

__device__ __forceinline__ float silu_f(float v) {
    return v / (1.0f + __expf(-v));
}

__global__ void __launch_bounds__(THREADS)
conv_silu_kernel(const float* __restrict__ x,
                 const float* __restrict__ cache,
                 const float* __restrict__ w,
                 float* __restrict__ out)
{
    const int b  = blockIdx.z;
    const int t0 = blockIdx.y * TS;
    const int d  = (blockIdx.x * THREADS + threadIdx.x) * 4;   // channel group start

    // Per-channel taps: weight is (D, K) row-major.
    const float4 wr0 = *reinterpret_cast<const float4*>(w + (size_t)(d + 0) * KK);
    const float4 wr1 = *reinterpret_cast<const float4*>(w + (size_t)(d + 1) * KK);
    const float4 wr2 = *reinterpret_cast<const float4*>(w + (size_t)(d + 2) * KK);
    const float4 wr3 = *reinterpret_cast<const float4*>(w + (size_t)(d + 3) * KK);

    // Sliding window: m3 = X[t-3], m2 = X[t-2], m1 = X[t-1] (per-channel float4)
    float4 m3, m2, m1;
    const float* xb = x + (size_t)b * LL * DD + d;   // x[b, 0, d]

    if (t0 == 0) {
        // Seed from cache[b, d+j, kk], kk = 1,2,3  (cache layout (B,D,K))
        const float* cb = cache + ((size_t)b * DD + d) * KK;
        m3 = make_float4(cb[0*KK + 1], cb[1*KK + 1], cb[2*KK + 1], cb[3*KK + 1]);
        m2 = make_float4(cb[0*KK + 2], cb[1*KK + 2], cb[2*KK + 2], cb[3*KK + 2]);
        m1 = make_float4(cb[0*KK + 3], cb[1*KK + 3], cb[2*KK + 3], cb[3*KK + 3]);
    } else {
        m3 = *reinterpret_cast<const float4*>(xb + (size_t)(t0 - 3) * DD);
        m2 = *reinterpret_cast<const float4*>(xb + (size_t)(t0 - 2) * DD);
        m1 = *reinterpret_cast<const float4*>(xb + (size_t)(t0 - 1) * DD);
    }

    // Route channel group to q / k / v segment
    float* obase;
    int seg_d, seg_w;
    size_t boff;
    if (d < QK_W) {
        obase = out;                 seg_d = d;          seg_w = QK_W;
        boff  = (size_t)b * LL * QK_W;
    } else if (d < 2 * QK_W) {
        obase = out + Q_SIZE;        seg_d = d - QK_W;   seg_w = QK_W;
        boff  = (size_t)b * LL * QK_W;
    } else {
        obase = out + 2 * Q_SIZE;    seg_d = d - 2*QK_W; seg_w = V_W;
        boff  = (size_t)b * LL * V_W;
    }
    float* op = obase + boff + (size_t)t0 * seg_w + seg_d;
    const float* xp = xb + (size_t)t0 * DD;

    #pragma unroll 1
    for (int o = 0; o < TS / UNR; o++) {
        #pragma unroll
        for (int i = 0; i < UNR; i++) {
            const float4 cur = *reinterpret_cast<const float4*>(xp + (size_t)i * DD);

            float4 y;
            y.x = wr0.x * m3.x + wr0.y * m2.x + wr0.z * m1.x + wr0.w * cur.x;
            y.y = wr1.x * m3.y + wr1.y * m2.y + wr1.z * m1.y + wr1.w * cur.y;
            y.z = wr2.x * m3.z + wr2.y * m2.z + wr2.z * m1.z + wr2.w * cur.z;
            y.w = wr3.x * m3.w + wr3.y * m2.w + wr3.z * m1.w + wr3.w * cur.w;

            y.x = silu_f(y.x);
            y.y = silu_f(y.y);
            y.z = silu_f(y.z);
            y.w = silu_f(y.w);

            // streaming store (written once, never re-read)
            __stcs(reinterpret_cast<float4*>(op + (size_t)i * seg_w), y);

            m3 = m2; m2 = m1; m1 = cur;
        }
        xp += (size_t)UNR * DD;
        op += (size_t)UNR * seg_w;
    }

    // Fused new-cache write: last chunk's window holds rows L-3..L-1 (m3,m2,m1).
    // Row L-4 is reloaded (L2-hot, just streamed through).
    if (t0 == LL - TS) {
        const float4 r4 = *reinterpret_cast<const float4*>(xb + (size_t)(LL - 4) * DD);
        float* cp = out + CACHE_OFF + ((size_t)b * DD + d) * KK;
        *reinterpret_cast<float4*>(cp + 0 * KK) = make_float4(r4.x, m3.x, m2.x, m1.x);
        *reinterpret_cast<float4*>(cp + 1 * KK) = make_float4(r4.y, m3.y, m2.y, m1.y);
        *reinterpret_cast<float4*>(cp + 2 * KK) = make_float4(r4.z, m3.z, m2.z, m1.z);
        *reinterpret_cast<float4*>(cp + 3 * KK) = make_float4(r4.w, m3.w, m2.w, m1.w);
    }
}

extern "C" void kernel_launch(void* const* d_in, const int* in_sizes, int n_in,
                              void* d_out, int out_size)
{
    const float* x     = (const float*)d_in[0];
    const float* cache = (const float*)d_in[1];
    const float* w     = (const float*)d_in[2];
    float* out = (float*)d_out;

    dim3 grid(DD / (4 * THREADS), LL / TS, BB);   // (8, 32, 4)
    conv_silu_kernel<<<grid, THREADS>>>(x, cache, w, out);
}

// round 6
// speedup vs baseline: 1.2173x; 1.1977x over previous
#include <cuda_runtime.h>
#include <cuda_bf16.h>

// Problem constants
#define BB 4
#define LL 2048
#define DD 8192
#define KK 4
#define TS 64           // timesteps per thread (sliding window)
#define UNR 4           // inner unroll (caps in-flight load buffer regs)
#define THREADS 128     // threads per block; each owns 4 channels (float4)

// Output layout: [q (B,L,2048) | k (B,L,2048) | v (B,L,4096) | new_cache (B,D,4)]
#define QK_W 2048
#define V_W  4096
#define Q_SIZE   ((size_t)BB * LL * QK_W)          // 16,777,216
#define V_SIZE   ((size_t)BB * LL * V_W)           // 33,554,432
#define CACHE_OFF (2 * Q_SIZE + V_SIZE)            // 67,108,864

// silu(x) = x * sigmoid(x) = 0.5*x*(1 + tanh(x/2))  — single MUFU via tanh.approx
__device__ __forceinline__ float silu_f(float v) {
    float t;
    asm("tanh.approx.f32 %0, %1;" : "=f"(t) : "f"(0.5f * v));
    return 0.5f * v * (1.0f + t);
}

__device__ __forceinline__ float4 ldcs4(const float* p) {
    return __ldcs(reinterpret_cast<const float4*>(p));
}

__global__ void __launch_bounds__(THREADS, 10)
conv_silu_kernel(const float* __restrict__ x,
                 const float* __restrict__ cache,
                 const float* __restrict__ w,
                 float* __restrict__ out)
{
    const int b  = blockIdx.z;
    const int t0 = blockIdx.y * TS;
    const int d  = (blockIdx.x * THREADS + threadIdx.x) * 4;   // channel group start

    // Per-channel taps: weight is (D, K) row-major.
    const float4 wr0 = *reinterpret_cast<const float4*>(w + (size_t)(d + 0) * KK);
    const float4 wr1 = *reinterpret_cast<const float4*>(w + (size_t)(d + 1) * KK);
    const float4 wr2 = *reinterpret_cast<const float4*>(w + (size_t)(d + 2) * KK);
    const float4 wr3 = *reinterpret_cast<const float4*>(w + (size_t)(d + 3) * KK);

    // Sliding window: m3 = X[t-3], m2 = X[t-2], m1 = X[t-1] (per-channel float4)
    float4 m3, m2, m1;
    const float* xb = x + (size_t)b * LL * DD + d;   // x[b, 0, d]

    if (t0 == 0) {
        // Seed from cache[b, d+j, kk], kk = 1,2,3  (cache layout (B,D,K))
        const float* cb = cache + ((size_t)b * DD + d) * KK;
        m3 = make_float4(cb[0*KK + 1], cb[1*KK + 1], cb[2*KK + 1], cb[3*KK + 1]);
        m2 = make_float4(cb[0*KK + 2], cb[1*KK + 2], cb[2*KK + 2], cb[3*KK + 2]);
        m1 = make_float4(cb[0*KK + 3], cb[1*KK + 3], cb[2*KK + 3], cb[3*KK + 3]);
    } else {
        m3 = ldcs4(xb + (size_t)(t0 - 3) * DD);
        m2 = ldcs4(xb + (size_t)(t0 - 2) * DD);
        m1 = ldcs4(xb + (size_t)(t0 - 1) * DD);
    }

    // Route channel group to q / k / v segment
    float* obase;
    int seg_d, seg_w;
    size_t boff;
    if (d < QK_W) {
        obase = out;                 seg_d = d;          seg_w = QK_W;
        boff  = (size_t)b * LL * QK_W;
    } else if (d < 2 * QK_W) {
        obase = out + Q_SIZE;        seg_d = d - QK_W;   seg_w = QK_W;
        boff  = (size_t)b * LL * QK_W;
    } else {
        obase = out + 2 * Q_SIZE;    seg_d = d - 2*QK_W; seg_w = V_W;
        boff  = (size_t)b * LL * V_W;
    }
    float* op = obase + boff + (size_t)t0 * seg_w + seg_d;
    const float* xp = xb + (size_t)t0 * DD;

    #pragma unroll 1
    for (int o = 0; o < TS / UNR; o++) {
        // Front-batch the UNR independent loads (MLP)
        float4 cur[UNR];
        #pragma unroll
        for (int i = 0; i < UNR; i++)
            cur[i] = ldcs4(xp + (size_t)i * DD);

        #pragma unroll
        for (int i = 0; i < UNR; i++) {
            const float4 c = cur[i];
            float4 y;
            y.x = wr0.x * m3.x + wr0.y * m2.x + wr0.z * m1.x + wr0.w * c.x;
            y.y = wr1.x * m3.y + wr1.y * m2.y + wr1.z * m1.y + wr1.w * c.y;
            y.z = wr2.x * m3.z + wr2.y * m2.z + wr2.z * m1.z + wr2.w * c.z;
            y.w = wr3.x * m3.w + wr3.y * m2.w + wr3.z * m1.w + wr3.w * c.w;

            y.x = silu_f(y.x);
            y.y = silu_f(y.y);
            y.z = silu_f(y.z);
            y.w = silu_f(y.w);

            __stcs(reinterpret_cast<float4*>(op + (size_t)i * seg_w), y);

            m3 = m2; m2 = m1; m1 = c;
        }
        xp += (size_t)UNR * DD;
        op += (size_t)UNR * seg_w;
    }

    // Fused new-cache write: last chunk's window holds rows L-3..L-1 (m3,m2,m1).
    if (t0 == LL - TS) {
        const float4 r4 = ldcs4(xb + (size_t)(LL - 4) * DD);
        float* cp = out + CACHE_OFF + ((size_t)b * DD + d) * KK;
        *reinterpret_cast<float4*>(cp + 0 * KK) = make_float4(r4.x, m3.x, m2.x, m1.x);
        *reinterpret_cast<float4*>(cp + 1 * KK) = make_float4(r4.y, m3.y, m2.y, m1.y);
        *reinterpret_cast<float4*>(cp + 2 * KK) = make_float4(r4.z, m3.z, m2.z, m1.z);
        *reinterpret_cast<float4*>(cp + 3 * KK) = make_float4(r4.w, m3.w, m2.w, m1.w);
    }
}

extern "C" void kernel_launch(void* const* d_in, const int* in_sizes, int n_in,
                              void* d_out, int out_size)
{
    const float* x     = (const float*)d_in[0];
    const float* cache = (const float*)d_in[1];
    const float* w     = (const float*)d_in[2];
    float* out = (float*)d_out;

    dim3 grid(DD / (4 * THREADS), LL / TS, BB);   // (16, 32, 4) = 2048 CTAs
    conv_silu_kernel<<<grid, THREADS>>>(x, cache, w, out);
}

// round 7
// speedup vs baseline: 1.3119x; 1.0777x over previous
#include <cuda_runtime.h>
#include <cuda_bf16.h>

// Problem constants
#define BB 4
#define LL 2048
#define DD 8192
#define KK 4
#define TS 32           // timesteps per tile (smaller => finer waves, less tail waste)
#define UNR 4           // inner unroll (caps in-flight load buffer regs)
#define THREADS 128     // threads per block; each owns 4 channels (float4)

// Output layout: [q (B,L,2048) | k (B,L,2048) | v (B,L,4096) | new_cache (B,D,4)]
#define QK_W 2048
#define V_W  4096
#define Q_SIZE   ((size_t)BB * LL * QK_W)          // 16,777,216
#define V_SIZE   ((size_t)BB * LL * V_W)           // 33,554,432
#define CACHE_OFF (2 * Q_SIZE + V_SIZE)            // 67,108,864

// silu(x) = x * sigmoid(x) = 0.5*x*(1 + tanh(x/2))  — single MUFU via tanh.approx
__device__ __forceinline__ float silu_f(float v) {
    float t;
    asm("tanh.approx.f32 %0, %1;" : "=f"(t) : "f"(0.5f * v));
    return 0.5f * v * (1.0f + t);
}

__device__ __forceinline__ float4 ldcs4(const float* p) {
    return __ldcs(reinterpret_cast<const float4*>(p));
}

__global__ void __launch_bounds__(THREADS, 10)
conv_silu_kernel(const float* __restrict__ x,
                 const float* __restrict__ cache,
                 const float* __restrict__ w,
                 float* __restrict__ out)
{
    const int b  = blockIdx.z;
    const int t0 = blockIdx.y * TS;
    const int d  = (blockIdx.x * THREADS + threadIdx.x) * 4;   // channel group start

    // Per-channel taps: weight is (D, K) row-major.
    const float4 wr0 = *reinterpret_cast<const float4*>(w + (size_t)(d + 0) * KK);
    const float4 wr1 = *reinterpret_cast<const float4*>(w + (size_t)(d + 1) * KK);
    const float4 wr2 = *reinterpret_cast<const float4*>(w + (size_t)(d + 2) * KK);
    const float4 wr3 = *reinterpret_cast<const float4*>(w + (size_t)(d + 3) * KK);

    // Sliding window: m3 = X[t-3], m2 = X[t-2], m1 = X[t-1] (per-channel float4)
    float4 m3, m2, m1;
    const float* xb = x + (size_t)b * LL * DD + d;   // x[b, 0, d]

    if (t0 == 0) {
        // Seed from cache[b, d+j, kk], kk = 1,2,3  (cache layout (B,D,K))
        const float* cb = cache + ((size_t)b * DD + d) * KK;
        m3 = make_float4(cb[0*KK + 1], cb[1*KK + 1], cb[2*KK + 1], cb[3*KK + 1]);
        m2 = make_float4(cb[0*KK + 2], cb[1*KK + 2], cb[2*KK + 2], cb[3*KK + 2]);
        m1 = make_float4(cb[0*KK + 3], cb[1*KK + 3], cb[2*KK + 3], cb[3*KK + 3]);
    } else {
        m3 = ldcs4(xb + (size_t)(t0 - 3) * DD);
        m2 = ldcs4(xb + (size_t)(t0 - 2) * DD);
        m1 = ldcs4(xb + (size_t)(t0 - 1) * DD);
    }

    // Route channel group to q / k / v segment
    float* obase;
    int seg_d, seg_w;
    size_t boff;
    if (d < QK_W) {
        obase = out;                 seg_d = d;          seg_w = QK_W;
        boff  = (size_t)b * LL * QK_W;
    } else if (d < 2 * QK_W) {
        obase = out + Q_SIZE;        seg_d = d - QK_W;   seg_w = QK_W;
        boff  = (size_t)b * LL * QK_W;
    } else {
        obase = out + 2 * Q_SIZE;    seg_d = d - 2*QK_W; seg_w = V_W;
        boff  = (size_t)b * LL * V_W;
    }
    float* op = obase + boff + (size_t)t0 * seg_w + seg_d;
    const float* xp = xb + (size_t)t0 * DD;

    #pragma unroll 1
    for (int o = 0; o < TS / UNR; o++) {
        // Front-batch the UNR independent loads (MLP)
        float4 cur[UNR];
        #pragma unroll
        for (int i = 0; i < UNR; i++)
            cur[i] = ldcs4(xp + (size_t)i * DD);

        #pragma unroll
        for (int i = 0; i < UNR; i++) {
            const float4 c = cur[i];
            float4 y;
            y.x = wr0.x * m3.x + wr0.y * m2.x + wr0.z * m1.x + wr0.w * c.x;
            y.y = wr1.x * m3.y + wr1.y * m2.y + wr1.z * m1.y + wr1.w * c.y;
            y.z = wr2.x * m3.z + wr2.y * m2.z + wr2.z * m1.z + wr2.w * c.z;
            y.w = wr3.x * m3.w + wr3.y * m2.w + wr3.z * m1.w + wr3.w * c.w;

            y.x = silu_f(y.x);
            y.y = silu_f(y.y);
            y.z = silu_f(y.z);
            y.w = silu_f(y.w);

            __stcs(reinterpret_cast<float4*>(op + (size_t)i * seg_w), y);

            m3 = m2; m2 = m1; m1 = c;
        }
        xp += (size_t)UNR * DD;
        op += (size_t)UNR * seg_w;
    }

    // Fused new-cache write: last chunk's window holds rows L-3..L-1 (m3,m2,m1).
    if (t0 == LL - TS) {
        const float4 r4 = ldcs4(xb + (size_t)(LL - 4) * DD);
        float* cp = out + CACHE_OFF + ((size_t)b * DD + d) * KK;
        *reinterpret_cast<float4*>(cp + 0 * KK) = make_float4(r4.x, m3.x, m2.x, m1.x);
        *reinterpret_cast<float4*>(cp + 1 * KK) = make_float4(r4.y, m3.y, m2.y, m1.y);
        *reinterpret_cast<float4*>(cp + 2 * KK) = make_float4(r4.z, m3.z, m2.z, m1.z);
        *reinterpret_cast<float4*>(cp + 3 * KK) = make_float4(r4.w, m3.w, m2.w, m1.w);
    }
}

extern "C" void kernel_launch(void* const* d_in, const int* in_sizes, int n_in,
                              void* d_out, int out_size)
{
    const float* x     = (const float*)d_in[0];
    const float* cache = (const float*)d_in[1];
    const float* w     = (const float*)d_in[2];
    float* out = (float*)d_out;

    dim3 grid(DD / (4 * THREADS), LL / TS, BB);   // (16, 64, 4) = 4096 CTAs
    conv_silu_kernel<<<grid, THREADS>>>(x, cache, w, out);
}

// round 9
// speedup vs baseline: 1.3171x; 1.0040x over previous
#include <cuda_runtime.h>
#include <cuda_bf16.h>

// Problem constants
#define BB 4
#define LL 2048
#define DD 8192
#define KK 4
#define TS 16           // timesteps per tile (fine quantum; halo served from L2)
#define UNR 4           // inner unroll (caps in-flight load buffer regs)
#define THREADS 128     // threads per block; each owns 4 channels (float4)

// Output layout: [q (B,L,2048) | k (B,L,2048) | v (B,L,4096) | new_cache (B,D,4)]
#define QK_W 2048
#define V_W  4096
#define Q_SIZE   ((size_t)BB * LL * QK_W)          // 16,777,216
#define V_SIZE   ((size_t)BB * LL * V_W)           // 33,554,432
#define CACHE_OFF (2 * Q_SIZE + V_SIZE)            // 67,108,864

// silu(x) = x * sigmoid(x) = 0.5*x*(1 + tanh(x/2))  — single MUFU via tanh.approx
__device__ __forceinline__ float silu_f(float v) {
    float t;
    asm("tanh.approx.f32 %0, %1;" : "=f"(t) : "f"(0.5f * v));
    return 0.5f * v * (1.0f + t);
}

// Default-policy vector load: x lines stay L2-cacheable so the t-adjacent
// tile's halo reads hit L2 instead of DRAM.
__device__ __forceinline__ float4 ld4(const float* p) {
    return *reinterpret_cast<const float4*>(p);
}

__global__ void __launch_bounds__(THREADS, 10)
conv_silu_kernel(const float* __restrict__ x,
                 const float* __restrict__ cache,
                 const float* __restrict__ w,
                 float* __restrict__ out)
{
    const int b  = blockIdx.z;
    const int t0 = blockIdx.y * TS;
    const int d  = (blockIdx.x * THREADS + threadIdx.x) * 4;   // channel group start

    // Per-channel taps: weight is (D, K) row-major.
    const float4 wr0 = *reinterpret_cast<const float4*>(w + (size_t)(d + 0) * KK);
    const float4 wr1 = *reinterpret_cast<const float4*>(w + (size_t)(d + 1) * KK);
    const float4 wr2 = *reinterpret_cast<const float4*>(w + (size_t)(d + 2) * KK);
    const float4 wr3 = *reinterpret_cast<const float4*>(w + (size_t)(d + 3) * KK);

    // Sliding window: m3 = X[t-3], m2 = X[t-2], m1 = X[t-1] (per-channel float4)
    float4 m3, m2, m1;
    const float* xb = x + (size_t)b * LL * DD + d;   // x[b, 0, d]

    if (t0 == 0) {
        // Seed from cache[b, d+j, kk], kk = 1,2,3  (cache layout (B,D,K))
        const float* cb = cache + ((size_t)b * DD + d) * KK;
        m3 = make_float4(cb[0*KK + 1], cb[1*KK + 1], cb[2*KK + 1], cb[3*KK + 1]);
        m2 = make_float4(cb[0*KK + 2], cb[1*KK + 2], cb[2*KK + 2], cb[3*KK + 2]);
        m1 = make_float4(cb[0*KK + 3], cb[1*KK + 3], cb[2*KK + 3], cb[3*KK + 3]);
    } else {
        m3 = ld4(xb + (size_t)(t0 - 3) * DD);
        m2 = ld4(xb + (size_t)(t0 - 2) * DD);
        m1 = ld4(xb + (size_t)(t0 - 1) * DD);
    }

    // Route channel group to q / k / v segment
    float* obase;
    int seg_d, seg_w;
    size_t boff;
    if (d < QK_W) {
        obase = out;                 seg_d = d;          seg_w = QK_W;
        boff  = (size_t)b * LL * QK_W;
    } else if (d < 2 * QK_W) {
        obase = out + Q_SIZE;        seg_d = d - QK_W;   seg_w = QK_W;
        boff  = (size_t)b * LL * QK_W;
    } else {
        obase = out + 2 * Q_SIZE;    seg_d = d - 2*QK_W; seg_w = V_W;
        boff  = (size_t)b * LL * V_W;
    }
    float* op = obase + boff + (size_t)t0 * seg_w + seg_d;
    const float* xp = xb + (size_t)t0 * DD;

    #pragma unroll 1
    for (int o = 0; o < TS / UNR; o++) {
        // Front-batch the UNR independent loads (MLP)
        float4 cur[UNR];
        #pragma unroll
        for (int i = 0; i < UNR; i++)
            cur[i] = ld4(xp + (size_t)i * DD);

        #pragma unroll
        for (int i = 0; i < UNR; i++) {
            const float4 c = cur[i];
            float4 y;
            y.x = wr0.x * m3.x + wr0.y * m2.x + wr0.z * m1.x + wr0.w * c.x;
            y.y = wr1.x * m3.y + wr1.y * m2.y + wr1.z * m1.y + wr1.w * c.y;
            y.z = wr2.x * m3.z + wr2.y * m2.z + wr2.z * m1.z + wr2.w * c.z;
            y.w = wr3.x * m3.w + wr3.y * m2.w + wr3.z * m1.w + wr3.w * c.w;

            y.x = silu_f(y.x);
            y.y = silu_f(y.y);
            y.z = silu_f(y.z);
            y.w = silu_f(y.w);

            __stcs(reinterpret_cast<float4*>(op + (size_t)i * seg_w), y);

            m3 = m2; m2 = m1; m1 = c;
        }
        xp += (size_t)UNR * DD;
        op += (size_t)UNR * seg_w;
    }

    // Fused new-cache write: last chunk's window holds rows L-3..L-1 (m3,m2,m1).
    if (t0 == LL - TS) {
        const float4 r4 = ld4(xb + (size_t)(LL - 4) * DD);
        float* cp = out + CACHE_OFF + ((size_t)b * DD + d) * KK;
        *reinterpret_cast<float4*>(cp + 0 * KK) = make_float4(r4.x, m3.x, m2.x, m1.x);
        *reinterpret_cast<float4*>(cp + 1 * KK) = make_float4(r4.y, m3.y, m2.y, m1.y);
        *reinterpret_cast<float4*>(cp + 2 * KK) = make_float4(r4.z, m3.z, m2.z, m1.z);
        *reinterpret_cast<float4*>(cp + 3 * KK) = make_float4(r4.w, m3.w, m2.w, m1.w);
    }
}

extern "C" void kernel_launch(void* const* d_in, const int* in_sizes, int n_in,
                              void* d_out, int out_size)
{
    const float* x     = (const float*)d_in[0];
    const float* cache = (const float*)d_in[1];
    const float* w     = (const float*)d_in[2];
    float* out = (float*)d_out;

    dim3 grid(DD / (4 * THREADS), LL / TS, BB);   // (16, 128, 4) = 8192 CTAs
    conv_silu_kernel<<<grid, THREADS>>>(x, cache, w, out);
}

// round 10
// speedup vs baseline: 1.4463x; 1.0980x over previous
#include <cuda_runtime.h>
#include <cuda_bf16.h>

// Problem constants
#define BB 4
#define LL 2048
#define DD 8192
#define KK 4
#define TS 32           // timesteps per tile
#define UNR 8           // inner unroll: 8-load burst then 8-store burst
#define THREADS 128     // threads per block; each owns 4 channels (float4)

// Output layout: [q (B,L,2048) | k (B,L,2048) | v (B,L,4096) | new_cache (B,D,4)]
#define QK_W 2048
#define V_W  4096
#define Q_SIZE   ((size_t)BB * LL * QK_W)          // 16,777,216
#define V_SIZE   ((size_t)BB * LL * V_W)           // 33,554,432
#define CACHE_OFF (2 * Q_SIZE + V_SIZE)            // 67,108,864

// silu(x) = x * sigmoid(x) = 0.5*x*(1 + tanh(x/2))  — single MUFU via tanh.approx
__device__ __forceinline__ float silu_f(float v) {
    float t;
    asm("tanh.approx.f32 %0, %1;" : "=f"(t) : "f"(0.5f * v));
    return 0.5f * v * (1.0f + t);
}

__device__ __forceinline__ float4 ld4(const float* p) {
    return *reinterpret_cast<const float4*>(p);
}

__global__ void __launch_bounds__(THREADS, 8)
conv_silu_kernel(const float* __restrict__ x,
                 const float* __restrict__ cache,
                 const float* __restrict__ w,
                 float* __restrict__ out)
{
    const int b  = blockIdx.z;
    const int t0 = blockIdx.y * TS;
    const int d  = (blockIdx.x * THREADS + threadIdx.x) * 4;   // channel group start

    // Per-channel taps: weight is (D, K) row-major.
    const float4 wr0 = *reinterpret_cast<const float4*>(w + (size_t)(d + 0) * KK);
    const float4 wr1 = *reinterpret_cast<const float4*>(w + (size_t)(d + 1) * KK);
    const float4 wr2 = *reinterpret_cast<const float4*>(w + (size_t)(d + 2) * KK);
    const float4 wr3 = *reinterpret_cast<const float4*>(w + (size_t)(d + 3) * KK);

    // Sliding window: m3 = X[t-3], m2 = X[t-2], m1 = X[t-1] (per-channel float4)
    float4 m3, m2, m1;
    const float* xb = x + (size_t)b * LL * DD + d;   // x[b, 0, d]

    if (t0 == 0) {
        // Seed from cache[b, d+j, kk], kk = 1,2,3  (cache layout (B,D,K))
        const float* cb = cache + ((size_t)b * DD + d) * KK;
        m3 = make_float4(cb[0*KK + 1], cb[1*KK + 1], cb[2*KK + 1], cb[3*KK + 1]);
        m2 = make_float4(cb[0*KK + 2], cb[1*KK + 2], cb[2*KK + 2], cb[3*KK + 2]);
        m1 = make_float4(cb[0*KK + 3], cb[1*KK + 3], cb[2*KK + 3], cb[3*KK + 3]);
    } else {
        m3 = ld4(xb + (size_t)(t0 - 3) * DD);
        m2 = ld4(xb + (size_t)(t0 - 2) * DD);
        m1 = ld4(xb + (size_t)(t0 - 1) * DD);
    }

    // Route channel group to q / k / v segment
    float* obase;
    int seg_d, seg_w;
    size_t boff;
    if (d < QK_W) {
        obase = out;                 seg_d = d;          seg_w = QK_W;
        boff  = (size_t)b * LL * QK_W;
    } else if (d < 2 * QK_W) {
        obase = out + Q_SIZE;        seg_d = d - QK_W;   seg_w = QK_W;
        boff  = (size_t)b * LL * QK_W;
    } else {
        obase = out + 2 * Q_SIZE;    seg_d = d - 2*QK_W; seg_w = V_W;
        boff  = (size_t)b * LL * V_W;
    }
    float* op = obase + boff + (size_t)t0 * seg_w + seg_d;
    const float* xp = xb + (size_t)t0 * DD;

    #pragma unroll 1
    for (int o = 0; o < TS / UNR; o++) {
        // ---- read burst: UNR independent LDG.128 ----
        float4 cur[UNR];
        #pragma unroll
        for (int i = 0; i < UNR; i++)
            cur[i] = ld4(xp + (size_t)i * DD);

        // ---- compute all UNR outputs (no stores interleaved) ----
        float4 yv[UNR];
        #pragma unroll
        for (int i = 0; i < UNR; i++) {
            const float4 c = cur[i];
            float4 y;
            y.x = wr0.x * m3.x + wr0.y * m2.x + wr0.z * m1.x + wr0.w * c.x;
            y.y = wr1.x * m3.y + wr1.y * m2.y + wr1.z * m1.y + wr1.w * c.y;
            y.z = wr2.x * m3.z + wr2.y * m2.z + wr2.z * m1.z + wr2.w * c.z;
            y.w = wr3.x * m3.w + wr3.y * m2.w + wr3.z * m1.w + wr3.w * c.w;
            y.x = silu_f(y.x);
            y.y = silu_f(y.y);
            y.z = silu_f(y.z);
            y.w = silu_f(y.w);
            yv[i] = y;
            m3 = m2; m2 = m1; m1 = c;
        }

        // ---- write burst: UNR STG.128 ----
        #pragma unroll
        for (int i = 0; i < UNR; i++)
            __stcs(reinterpret_cast<float4*>(op + (size_t)i * seg_w), yv[i]);

        xp += (size_t)UNR * DD;
        op += (size_t)UNR * seg_w;
    }

    // Fused new-cache write: last chunk's window holds rows L-3..L-1 (m3,m2,m1).
    if (t0 == LL - TS) {
        const float4 r4 = ld4(xb + (size_t)(LL - 4) * DD);
        float* cp = out + CACHE_OFF + ((size_t)b * DD + d) * KK;
        *reinterpret_cast<float4*>(cp + 0 * KK) = make_float4(r4.x, m3.x, m2.x, m1.x);
        *reinterpret_cast<float4*>(cp + 1 * KK) = make_float4(r4.y, m3.y, m2.y, m1.y);
        *reinterpret_cast<float4*>(cp + 2 * KK) = make_float4(r4.z, m3.z, m2.z, m1.z);
        *reinterpret_cast<float4*>(cp + 3 * KK) = make_float4(r4.w, m3.w, m2.w, m1.w);
    }
}

extern "C" void kernel_launch(void* const* d_in, const int* in_sizes, int n_in,
                              void* d_out, int out_size)
{
    const float* x     = (const float*)d_in[0];
    const float* cache = (const float*)d_in[1];
    const float* w     = (const float*)d_in[2];
    float* out = (float*)d_out;

    dim3 grid(DD / (4 * THREADS), LL / TS, BB);   // (16, 64, 4) = 4096 CTAs
    conv_silu_kernel<<<grid, THREADS>>>(x, cache, w, out);
}

// round 11
// speedup vs baseline: 1.4807x; 1.0238x over previous
#include <cuda_runtime.h>
#include <cuda_bf16.h>

// Problem constants
#define BB 4
#define LL 2048
#define DD 8192
#define KK 4
#define TS 32           // timesteps per tile
#define UNR 16          // inner unroll: 16-load burst then 16-store burst (4KB/dir per warp)
#define THREADS 128     // threads per block; each owns 4 channels (float4)

// Output layout: [q (B,L,2048) | k (B,L,2048) | v (B,L,4096) | new_cache (B,D,4)]
#define QK_W 2048
#define V_W  4096
#define Q_SIZE   ((size_t)BB * LL * QK_W)          // 16,777,216
#define V_SIZE   ((size_t)BB * LL * V_W)           // 33,554,432
#define CACHE_OFF (2 * Q_SIZE + V_SIZE)            // 67,108,864

// silu(x) = x * sigmoid(x) = 0.5*x*(1 + tanh(x/2))  — single MUFU via tanh.approx
__device__ __forceinline__ float silu_f(float v) {
    float t;
    asm("tanh.approx.f32 %0, %1;" : "=f"(t) : "f"(0.5f * v));
    return 0.5f * v * (1.0f + t);
}

__device__ __forceinline__ float4 ld4(const float* p) {
    return *reinterpret_cast<const float4*>(p);
}

__global__ void __launch_bounds__(THREADS, 5)
conv_silu_kernel(const float* __restrict__ x,
                 const float* __restrict__ cache,
                 const float* __restrict__ w,
                 float* __restrict__ out)
{
    const int b  = blockIdx.z;
    const int t0 = blockIdx.y * TS;
    const int d  = (blockIdx.x * THREADS + threadIdx.x) * 4;   // channel group start

    // Per-channel taps: weight is (D, K) row-major.
    const float4 wr0 = *reinterpret_cast<const float4*>(w + (size_t)(d + 0) * KK);
    const float4 wr1 = *reinterpret_cast<const float4*>(w + (size_t)(d + 1) * KK);
    const float4 wr2 = *reinterpret_cast<const float4*>(w + (size_t)(d + 2) * KK);
    const float4 wr3 = *reinterpret_cast<const float4*>(w + (size_t)(d + 3) * KK);

    // Sliding window: m3 = X[t-3], m2 = X[t-2], m1 = X[t-1] (per-channel float4)
    float4 m3, m2, m1;
    const float* xb = x + (size_t)b * LL * DD + d;   // x[b, 0, d]

    if (t0 == 0) {
        // Seed from cache[b, d+j, kk], kk = 1,2,3  (cache layout (B,D,K))
        const float* cb = cache + ((size_t)b * DD + d) * KK;
        m3 = make_float4(cb[0*KK + 1], cb[1*KK + 1], cb[2*KK + 1], cb[3*KK + 1]);
        m2 = make_float4(cb[0*KK + 2], cb[1*KK + 2], cb[2*KK + 2], cb[3*KK + 2]);
        m1 = make_float4(cb[0*KK + 3], cb[1*KK + 3], cb[2*KK + 3], cb[3*KK + 3]);
    } else {
        m3 = ld4(xb + (size_t)(t0 - 3) * DD);
        m2 = ld4(xb + (size_t)(t0 - 2) * DD);
        m1 = ld4(xb + (size_t)(t0 - 1) * DD);
    }

    // Route channel group to q / k / v segment
    float* obase;
    int seg_d, seg_w;
    size_t boff;
    if (d < QK_W) {
        obase = out;                 seg_d = d;          seg_w = QK_W;
        boff  = (size_t)b * LL * QK_W;
    } else if (d < 2 * QK_W) {
        obase = out + Q_SIZE;        seg_d = d - QK_W;   seg_w = QK_W;
        boff  = (size_t)b * LL * QK_W;
    } else {
        obase = out + 2 * Q_SIZE;    seg_d = d - 2*QK_W; seg_w = V_W;
        boff  = (size_t)b * LL * V_W;
    }
    float* op = obase + boff + (size_t)t0 * seg_w + seg_d;
    const float* xp = xb + (size_t)t0 * DD;

    #pragma unroll 1
    for (int o = 0; o < TS / UNR; o++) {
        // ---- read burst: UNR independent LDG.128 ----
        float4 cur[UNR];
        #pragma unroll
        for (int i = 0; i < UNR; i++)
            cur[i] = ld4(xp + (size_t)i * DD);

        // ---- compute all UNR outputs in place (cur[i] dead after window update) ----
        #pragma unroll
        for (int i = 0; i < UNR; i++) {
            const float4 c = cur[i];
            float4 y;
            y.x = wr0.x * m3.x + wr0.y * m2.x + wr0.z * m1.x + wr0.w * c.x;
            y.y = wr1.x * m3.y + wr1.y * m2.y + wr1.z * m1.y + wr1.w * c.y;
            y.z = wr2.x * m3.z + wr2.y * m2.z + wr2.z * m1.z + wr2.w * c.z;
            y.w = wr3.x * m3.w + wr3.y * m2.w + wr3.z * m1.w + wr3.w * c.w;
            y.x = silu_f(y.x);
            y.y = silu_f(y.y);
            y.z = silu_f(y.z);
            y.w = silu_f(y.w);
            m3 = m2; m2 = m1; m1 = c;
            cur[i] = y;                      // overlay: reuse load buffer for outputs
        }

        // ---- write burst: UNR STG.128 ----
        #pragma unroll
        for (int i = 0; i < UNR; i++)
            __stcs(reinterpret_cast<float4*>(op + (size_t)i * seg_w), cur[i]);

        xp += (size_t)UNR * DD;
        op += (size_t)UNR * seg_w;
    }

    // Fused new-cache write: last chunk's window holds rows L-3..L-1 (m3,m2,m1).
    if (t0 == LL - TS) {
        const float4 r4 = ld4(xb + (size_t)(LL - 4) * DD);
        float* cp = out + CACHE_OFF + ((size_t)b * DD + d) * KK;
        *reinterpret_cast<float4*>(cp + 0 * KK) = make_float4(r4.x, m3.x, m2.x, m1.x);
        *reinterpret_cast<float4*>(cp + 1 * KK) = make_float4(r4.y, m3.y, m2.y, m1.y);
        *reinterpret_cast<float4*>(cp + 2 * KK) = make_float4(r4.z, m3.z, m2.z, m1.z);
        *reinterpret_cast<float4*>(cp + 3 * KK) = make_float4(r4.w, m3.w, m2.w, m1.w);
    }
}

extern "C" void kernel_launch(void* const* d_in, const int* in_sizes, int n_in,
                              void* d_out, int out_size)
{
    const float* x     = (const float*)d_in[0];
    const float* cache = (const float*)d_in[1];
    const float* w     = (const float*)d_in[2];
    float* out = (float*)d_out;

    dim3 grid(DD / (4 * THREADS), LL / TS, BB);   // (16, 64, 4) = 4096 CTAs
    conv_silu_kernel<<<grid, THREADS>>>(x, cache, w, out);
}